// round 15
// baseline (speedup 1.0000x reference)
#include <cuda_runtime.h>
#include <cuda_bf16.h>
#include <cstdint>

#define NR 2048
#define KDIM 512
#define DD 64
typedef unsigned long long ull;

// allocation-free scratch: fragment-order GEMM operands for kC + epilogue vectors
// gfA[mt 0..127][ks 0..7][lane 0..31][reg 0..3] : tf32(z)       (512 KB)
// gfB[nt 0..255][ks 0..7][lane 0..31][r 0..1]   : tf32(z*w3b)   (512 KB)
__device__ __align__(128) float gfA[128 * 8 * 128];
__device__ __align__(128) float gfB[256 * 8 * 64];
__device__ float g_a[NR];   // 0.5*a_i
__device__ float g_b[NR];   // 0.5*b_j

// ---------------- helpers ----------------
__device__ __forceinline__ float tanh_fast(float x) {
    float y; asm("tanh.approx.f32 %0, %1;" : "=f"(y) : "f"(x)); return y;
}
__device__ __forceinline__ float tf32r(float x) {
    unsigned r; asm("cvt.rna.tf32.f32 %0, %1;" : "=r"(r) : "f"(x));
    return __uint_as_float(r);
}
// sigmoid(sigmoid(acc + a + b)) with ha=0.5a, hb=0.5b.
// inner: sigma = 0.5+0.5t, t = tanh(x/2); outer: deg-5 Taylor in t (abs err < 1e-5)
__device__ __forceinline__ float dsig(float acc, float ha, float hb) {
    float t = tanh_fast(fmaf(0.5f, acc, ha) + hb);
    float p = fmaf(3.5318e-5f, t, 2.72792e-4f);
    p = fmaf(p, t, -2.007434e-3f);
    p = fmaf(p, t, -7.194604e-3f);
    p = fmaf(p, t, 0.117501856f);
    p = fmaf(p, t, 0.622459331f);
    return p;
}
__device__ __forceinline__ void cp16(uint32_t saddr, const void* g) {
    asm volatile("cp.async.cg.shared.global [%0], [%1], 16;" :: "r"(saddr), "l"(g));
}
__device__ __forceinline__ void cp_commit() { asm volatile("cp.async.commit_group;"); }
template <int N> __device__ __forceinline__ void cp_wait() {
    asm volatile("cp.async.wait_group %0;" :: "n"(N));
}

// warp-level tf32 MMA: D(16x8) += A(16x8) * B(8x8)
// Operands are raw fp32 registers: HW reads the tf32 bit-subset (truncation).
__device__ __forceinline__ void mma_tf32(float* c, float4 a, float2 b) {
    asm volatile(
        "mma.sync.aligned.m16n8k8.row.col.f32.tf32.tf32.f32 "
        "{%0,%1,%2,%3}, {%4,%5,%6,%7}, {%8,%9}, {%0,%1,%2,%3};"
        : "+f"(c[0]), "+f"(c[1]), "+f"(c[2]), "+f"(c[3])
        : "r"(__float_as_uint(a.x)), "r"(__float_as_uint(a.y)),
          "r"(__float_as_uint(a.z)), "r"(__float_as_uint(a.w)),
          "r"(__float_as_uint(b.x)), "r"(__float_as_uint(b.y)));
}

// ================ kernel B: z = x@W via mma.sync tf32 ================
// 128 blocks x 256 thr (8 warps). Block: 16 rows x 64 cols, K=512 in 8
// double-buffered chunks of 64, ONE barrier per chunk. Warp wid owns cols
// [8wid, 8wid+8) for full K; 4 independent accumulator chains (ks&3).
// Outputs: frag-order tf32(z)->gfA, tf32(z*w3b)->gfB, 0.5*a->g_a, 0.5*b->g_b.
#define AST 68   // 68 mod 32 = 4 -> A-frag banks 4*tg+tc : perm of 0..31
#define BST 72   // 72 mod 32 = 8 -> B-frag banks 8*tc+tg : perm of 0..31
__global__ __launch_bounds__(256) void kB(const float* __restrict__ x,
                                          const float* __restrict__ W,
                                          const float* __restrict__ W2,
                                          const float* __restrict__ W3) {
    __shared__ __align__(16) float sA[2][16][AST];
    __shared__ __align__(16) float sB[2][64][BST];
    __shared__ float u_s[DD], v_s[DD];
    __shared__ float redA[8][16], redB[8][16];

    const int tid = threadIdx.x;
    const int wid = tid >> 5, lane = tid & 31;
    const int tg = lane >> 2, tc = lane & 3;
    const int mt = blockIdx.x;
    const int rowBase = mt * 16;

    uint32_t sA_u = (uint32_t)__cvta_generic_to_shared(&sA[0][0][0]);
    uint32_t sB_u = (uint32_t)__cvta_generic_to_shared(&sB[0][0][0]);

    auto fill = [&](int buf, int kc) {
        {   // A: 16 rows x 16 float4 = 256 -> 1 per thread
            int row = tid >> 4, u = tid & 15;
            cp16(sA_u + (uint32_t)((buf * 16 + row) * AST + u * 4) * 4u,
                 x + (rowBase + row) * KDIM + kc + u * 4);
        }
        #pragma unroll
        for (int j = 0; j < 4; j++) {   // B: 64 k-rows x 16 float4 = 1024 -> 4/thread
            int f = tid + 256 * j;
            int k = f >> 4, u = f & 15;
            cp16(sB_u + (uint32_t)((buf * 64 + k) * BST + u * 4) * 4u,
                 W + (kc + k) * DD + u * 4);
        }
        cp_commit();
    };

    fill(0, 0);

    // u = W2[:64]@w3a, v = W2[64:]@w3a (overlapped with first cp.async fill)
    if (tid < 128) {
        int k = tid & 63, half = tid >> 6;
        const float* w2r = W2 + (half * 64 + k) * 64;
        float s = 0.f;
        #pragma unroll
        for (int j = 0; j < 64; j += 4) {
            float4 a = *(const float4*)(w2r + j);
            float4 b = *(const float4*)(W3 + j);
            s += a.x * b.x + a.y * b.y + a.z * b.z + a.w * b.w;
        }
        if (half == 0) u_s[k] = s; else v_s[k] = s;
    }

    float ac[4][4];
    #pragma unroll
    for (int q = 0; q < 4; q++)
        #pragma unroll
        for (int r = 0; r < 4; r++) ac[q][r] = 0.f;

    for (int c = 0; c < 8; c++) {
        int buf = c & 1;
        cp_wait<0>();          // fill(c) complete (issued before compute of c-1)
        __syncthreads();       // all warps done computing on buf^1 from iter c-1
        if (c < 7) fill(buf ^ 1, (c + 1) * 64);

        const float (*A)[AST] = sA[buf];
        const float (*B)[BST] = sB[buf];
        #pragma unroll
        for (int ks = 0; ks < 8; ks++) {
            int k0 = ks * 8;
            float4 a = make_float4(A[tg][k0 + tc],
                                   A[tg + 8][k0 + tc],
                                   A[tg][k0 + tc + 4],
                                   A[tg + 8][k0 + tc + 4]);
            float2 b = make_float2(B[k0 + tc][wid * 8 + tg],
                                   B[k0 + tc + 4][wid * 8 + tg]);
            mma_tf32(ac[ks & 3], a, b);
        }
    }

    // C frag: c0=(tg,2tc) c1=(tg,2tc+1) c2=(tg+8,2tc) c3=(tg+8,2tc+1)
    float zA0 = (ac[0][0] + ac[1][0]) + (ac[2][0] + ac[3][0]);  // row tg,  col 2tc
    float zA1 = (ac[0][1] + ac[1][1]) + (ac[2][1] + ac[3][1]);  // row tg,  col 2tc+1
    float zB0 = (ac[0][2] + ac[1][2]) + (ac[2][2] + ac[3][2]);  // row tg+8,col 2tc
    float zB1 = (ac[0][3] + ac[1][3]) + (ac[2][3] + ac[3][3]);  // row tg+8,col 2tc+1

    // ---- frag-order A stores: element (row, k): lane'=(row&7)*4+(k&3),
    // reg = 2*((k>>2)&1) + (row>>3&1). k = 8*wid + 2tc + j.
    {
        float zr[2][2] = {{tf32r(zA0), tf32r(zB0)}, {tf32r(zA1), tf32r(zB1)}};  // [j][rbit]
        float* baseA = gfA + (mt * 8 + wid) * 128;
        #pragma unroll
        for (int j = 0; j < 2; j++) {
            int kk = 2 * tc + j;
            int lanep = tg * 4 + (kk & 3);
            int regb = (kk >> 2) * 2;
            *(float2*)(baseA + lanep * 4 + regb) = make_float2(zr[j][0], zr[j][1]);
        }
    }
    // ---- frag-order B stores: element (rowZ, k): nt=2mt+rbit,
    // lane'=(rowZ&7)*4+(k&3), r=(k>>2)&1 -> elem lane'*2+r.
    {
        int col0 = wid * 8 + 2 * tc;
        float w3b0 = W3[DD + col0], w3b1 = W3[DD + col0 + 1];
        float zw[2][2] = {{tf32r(zA0 * w3b0), tf32r(zB0 * w3b0)},
                          {tf32r(zA1 * w3b1), tf32r(zB1 * w3b1)}};  // [j][rbit]
        #pragma unroll
        for (int j = 0; j < 2; j++) {
            int kk = 2 * tc + j;
            int lanep = tg * 4 + (kk & 3);
            int rB = kk >> 2;
            #pragma unroll
            for (int rbit = 0; rbit < 2; rbit++) {
                float* baseB = gfB + ((2 * mt + rbit) * 8 + wid) * 64;
                baseB[lanep * 2 + rB] = zw[j][rbit];
            }
        }
    }

    // a/b partials over this warp's 2 cols, rows tg and tg+8
    {
        int col0 = wid * 8 + 2 * tc;
        float u0 = u_s[col0], u1 = u_s[col0 + 1];
        float v0 = v_s[col0], v1 = v_s[col0 + 1];
        float rA0 = fmaxf(zA0, 0.f), rA1 = fmaxf(zA1, 0.f);
        float rB0 = fmaxf(zB0, 0.f), rB1 = fmaxf(zB1, 0.f);
        float paA = rA0 * u0 + rA1 * u1, pbA = rA0 * v0 + rA1 * v1;
        float paB = rB0 * u0 + rB1 * u1, pbB = rB0 * v0 + rB1 * v1;
        #pragma unroll
        for (int off = 1; off <= 2; off <<= 1) {
            paA += __shfl_down_sync(0xffffffffu, paA, off);
            pbA += __shfl_down_sync(0xffffffffu, pbA, off);
            paB += __shfl_down_sync(0xffffffffu, paB, off);
            pbB += __shfl_down_sync(0xffffffffu, pbB, off);
        }
        if (tc == 0) {
            redA[wid][tg] = paA; redA[wid][tg + 8] = paB;
            redB[wid][tg] = pbA; redB[wid][tg + 8] = pbB;
        }
    }
    __syncthreads();
    if (tid < 32) {
        int row = tid & 15;
        float s = 0.f;
        if (tid < 16) {
            #pragma unroll
            for (int w = 0; w < 8; w++) s += redA[w][row];
            g_a[rowBase + row] = 0.5f * s;
        } else {
            #pragma unroll
            for (int w = 0; w < 8; w++) s += redB[w][row];
            g_b[rowBase + row] = 0.5f * s;
        }
    }
}

// ================ kernel C: frag-order tf32 GEMM + fused double-sigmoid ================
// grid (16,16) x 256 thr (8 warps as 2 x 4). Tile 128x128, warp = 64x32 via 4x4
// m16n8k8 tiles, K=64 = 8 ksteps. Both A and B frag slices are CONTIGUOUS 32KB
// blocks of gfA/gfB -> one linear 64KB cp.async burst, then an all-SMEM mainloop
// (conflict-free LDS.128 / LDS.64). No LDG in the mma dependency path.
#define KC_SMEM 65536
__global__ __launch_bounds__(256) void kC(float* __restrict__ out) {
    extern __shared__ __align__(16) float smem[];
    float* sA = smem;           // 8192 floats: [mt 0..7][ks 0..7][128]
    float* sB = smem + 8192;    // 8192 floats: [nt 0..15][ks 0..7][64]

    const int tid = threadIdx.x;
    const int wid = tid >> 5, lane = tid & 31;
    const int warpRow = wid >> 2, warpCol = wid & 3;
    const int rowBase = blockIdx.y * 128, colBase = blockIdx.x * 128;
    const int tg = lane >> 2, tc = lane & 3;

    uint32_t s_u = (uint32_t)__cvta_generic_to_shared(smem);
    const float* srcA = gfA + blockIdx.y * 8192;
    const float* srcB = gfB + blockIdx.x * 8192;
    #pragma unroll
    for (int j = 0; j < 8; j++) {
        int f = tid + 256 * j;
        cp16(s_u + (uint32_t)f * 16u, srcA + f * 4);
    }
    #pragma unroll
    for (int j = 0; j < 8; j++) {
        int f = tid + 256 * j;
        cp16(s_u + 32768u + (uint32_t)f * 16u, srcB + f * 4);
    }
    cp_commit();

    // hoist hb loads to overlap the cp.async wait
    float hb0[4], hb1[4];
    #pragma unroll
    for (int n = 0; n < 4; n++) {
        int c0 = colBase + warpCol * 32 + n * 8 + tc * 2;
        hb0[n] = g_b[c0];
        hb1[n] = g_b[c0 + 1];
    }

    cp_wait<0>();
    __syncthreads();

    float acc[4][4][4];
    #pragma unroll
    for (int m = 0; m < 4; m++)
        #pragma unroll
        for (int n = 0; n < 4; n++)
            #pragma unroll
            for (int r = 0; r < 4; r++) acc[m][n][r] = 0.f;

    #pragma unroll
    for (int ks = 0; ks < 8; ks++) {
        float2 bf[4];
        #pragma unroll
        for (int n = 0; n < 4; n++)
            bf[n] = *(const float2*)(sB + ((warpCol * 4 + n) * 8 + ks) * 64 + lane * 2);
        float4 af[4];
        #pragma unroll
        for (int m = 0; m < 4; m++)
            af[m] = *(const float4*)(sA + ((warpRow * 4 + m) * 8 + ks) * 128 + lane * 4);
        #pragma unroll
        for (int m = 0; m < 4; m++)
            #pragma unroll
            for (int n = 0; n < 4; n++)
                mma_tf32(acc[m][n], af[m], bf[n]);
    }

    // ---- epilogue: double sigmoid + st.v2 ----
    #pragma unroll
    for (int m = 0; m < 4; m++) {
        int r0 = rowBase + warpRow * 64 + m * 16 + tg;
        float ha0 = g_a[r0], ha1 = g_a[r0 + 8];
        float* o0 = out + (long)r0 * NR + colBase + warpCol * 32 + tc * 2;
        float* o1 = o0 + 8L * NR;
        #pragma unroll
        for (int n = 0; n < 4; n++) {
            float* a4 = acc[m][n];
            float2 v0, v1;
            v0.x = dsig(a4[0], ha0, hb0[n]);
            v0.y = dsig(a4[1], ha0, hb1[n]);
            v1.x = dsig(a4[2], ha1, hb0[n]);
            v1.y = dsig(a4[3], ha1, hb1[n]);
            *(float2*)(o0 + n * 8) = v0;
            *(float2*)(o1 + n * 8) = v1;
        }
    }
}

extern "C" void kernel_launch(void* const* d_in, const int* in_sizes, int n_in,
                              void* d_out, int out_size) {
    const float* x  = (const float*)d_in[0];
    const float* W  = (const float*)d_in[1];
    const float* W2 = (const float*)d_in[2];
    const float* W3 = (const float*)d_in[3];
    float* out = (float*)d_out;
    cudaFuncSetAttribute(kC, cudaFuncAttributeMaxDynamicSharedMemorySize, KC_SMEM);
    kB<<<128, 256>>>(x, W, W2, W3);
    kC<<<dim3(16, 16), 256, KC_SMEM>>>(out);
}